// round 2
// baseline (speedup 1.0000x reference)
#include <cuda_runtime.h>
#include <float.h>

#define BB 32
#define QQ 300
#define NCLS 92
#define MM 50
#define NP (BB*QQ)      // 9600 pred rows
#define NT (BB*MM)      // 1600 target cols
#define M1 300          // m (columns in hungarian)
#define N1 50           // n (rows in hungarian)

// Normalized softmax probabilities, 9600 x 92 (3.53 MB scratch)
__device__ float g_probs[NP * NCLS];

// ---------------------------------------------------------------------------
// Kernel A: row softmax of logits. One warp per row.
// ---------------------------------------------------------------------------
__global__ void softmax_kernel(const float* __restrict__ logits) {
    int warp = (blockIdx.x * blockDim.x + threadIdx.x) >> 5;
    int lane = threadIdx.x & 31;
    if (warp >= NP) return;
    const float* row = logits + (size_t)warp * NCLS;
    float x0 = row[lane];
    float x1 = row[lane + 32];
    float x2 = (lane < NCLS - 64) ? row[lane + 64] : -FLT_MAX;
    float mx = fmaxf(fmaxf(x0, x1), x2);
    #pragma unroll
    for (int o = 16; o; o >>= 1) mx = fmaxf(mx, __shfl_xor_sync(0xffffffffu, mx, o));
    float e0 = expf(x0 - mx), e1 = expf(x1 - mx);
    float e2 = (lane < NCLS - 64) ? expf(x2 - mx) : 0.f;
    float s = e0 + e1 + e2;
    #pragma unroll
    for (int o = 16; o; o >>= 1) s += __shfl_xor_sync(0xffffffffu, s, o);
    float inv = 1.f / s;
    float* prow = g_probs + (size_t)warp * NCLS;
    prow[lane] = e0 * inv;
    prow[lane + 32] = e1 * inv;
    if (lane < NCLS - 64) prow[lane + 64] = e2 * inv;
}

// ---------------------------------------------------------------------------
// Kernel B: full cross cost matrix C[9600][1600].
// Tile: 16 preds x 64 targets per block; block (64,4), each thread 4 preds.
// ---------------------------------------------------------------------------
__global__ void cost_kernel(const float* __restrict__ pred_boxes,
                            const int*   __restrict__ tgt_labels,
                            const float* __restrict__ tgt_boxes,
                            float* __restrict__ Cout) {
    __shared__ float s_probs[16 * NCLS];
    __shared__ float s_pcx[16][4];   // pred cxcywh
    __shared__ float s_pxy[16][4];   // pred xyxy
    __shared__ float s_parea[16];
    __shared__ float s_tcx[64][4];
    __shared__ float s_txy[64][4];
    __shared__ float s_tarea[64];
    __shared__ int   s_tl[64];

    int tid = threadIdx.y * 64 + threadIdx.x;
    int p0 = blockIdx.x * 16;
    int t0 = blockIdx.y * 64;

    for (int i = tid; i < 16 * NCLS; i += 256) {
        int pp = i / NCLS, c = i - pp * NCLS;
        s_probs[pp * NCLS + c] = g_probs[(size_t)(p0 + pp) * NCLS + c];
    }
    if (tid < 16) {
        const float* b = pred_boxes + (size_t)(p0 + tid) * 4;
        float cx = b[0], cy = b[1], w = b[2], h = b[3];
        s_pcx[tid][0] = cx; s_pcx[tid][1] = cy; s_pcx[tid][2] = w; s_pcx[tid][3] = h;
        float x0 = cx - 0.5f * w, y0 = cy - 0.5f * h;
        float x1 = cx + 0.5f * w, y1 = cy + 0.5f * h;
        s_pxy[tid][0] = x0; s_pxy[tid][1] = y0; s_pxy[tid][2] = x1; s_pxy[tid][3] = y1;
        s_parea[tid] = (x1 - x0) * (y1 - y0);
    }
    if (tid < 64) {
        const float* b = tgt_boxes + (size_t)(t0 + tid) * 4;
        float cx = b[0], cy = b[1], w = b[2], h = b[3];
        s_tcx[tid][0] = cx; s_tcx[tid][1] = cy; s_tcx[tid][2] = w; s_tcx[tid][3] = h;
        float x0 = cx - 0.5f * w, y0 = cy - 0.5f * h;
        float x1 = cx + 0.5f * w, y1 = cy + 0.5f * h;
        s_txy[tid][0] = x0; s_txy[tid][1] = y0; s_txy[tid][2] = x1; s_txy[tid][3] = y1;
        s_tarea[tid] = (x1 - x0) * (y1 - y0);
        s_tl[tid] = tgt_labels[t0 + tid];
    }
    __syncthreads();

    int tx = threadIdx.x;
    int lab = s_tl[tx];
    float tcx = s_tcx[tx][0], tcy = s_tcx[tx][1], tw = s_tcx[tx][2], th = s_tcx[tx][3];
    float bx0 = s_txy[tx][0], by0 = s_txy[tx][1], bx1 = s_txy[tx][2], by1 = s_txy[tx][3];
    float areaB = s_tarea[tx];
    int col = t0 + tx;

    #pragma unroll
    for (int k = 0; k < 4; k++) {
        int pp = threadIdx.y + k * 4;
        float cc = -s_probs[pp * NCLS + lab];
        float cb = fabsf(s_pcx[pp][0] - tcx) + fabsf(s_pcx[pp][1] - tcy)
                 + fabsf(s_pcx[pp][2] - tw)  + fabsf(s_pcx[pp][3] - th);
        float ax0 = s_pxy[pp][0], ay0 = s_pxy[pp][1], ax1 = s_pxy[pp][2], ay1 = s_pxy[pp][3];
        float areaA = s_parea[pp];
        float ix0 = fmaxf(ax0, bx0), iy0 = fmaxf(ay0, by0);
        float ix1 = fminf(ax1, bx1), iy1 = fminf(ay1, by1);
        float iw = fmaxf(ix1 - ix0, 0.f), ih = fmaxf(iy1 - iy0, 0.f);
        float inter = iw * ih;
        float uni = areaA + areaB - inter;
        float iou = inter / uni;
        float ex0 = fminf(ax0, bx0), ey0 = fminf(ay0, by0);
        float ex1 = fmaxf(ax1, bx1), ey1 = fmaxf(ay1, by1);
        float ew = fmaxf(ex1 - ex0, 0.f), eh = fmaxf(ey1 - ey0, 0.f);
        float areaE = ew * eh;
        float giou = iou - (areaE - uni) / areaE;
        float c = 1.0f * cc + 5.0f * cb + 2.0f * (-giou);
        Cout[(size_t)(p0 + pp) * NT + col] = c;
    }
}

// ---------------------------------------------------------------------------
// Kernel C: Jonker-Volgenant Hungarian, one block per batch (32 blocks).
// cost is n=50 rows x m=300 cols in SMEM. 320 threads; thread j owns column j.
// ---------------------------------------------------------------------------
__global__ void hungarian_kernel(const float* __restrict__ Cg, float* __restrict__ out) {
    extern __shared__ float smem[];
    float* cost = smem;                     // 50*300
    float* u    = cost + N1 * M1;           // 51
    float* v    = u + (N1 + 1);             // 301
    float* minv = v + (M1 + 1);             // 301
    int* p    = (int*)(minv + (M1 + 1));    // 301
    int* way  = p + (M1 + 1);               // 301
    int* used = way + (M1 + 1);             // 301
    int* qrow = used + (M1 + 1);            // 50

    __shared__ int s_j0;
    __shared__ int s_j1;
    __shared__ float s_delta;
    __shared__ unsigned long long s_red[10];

    int b = blockIdx.x;
    int tid = threadIdx.x;

    // load per-batch cost (transposed diagonal slice): cost[i][j] = C[b*Q+j][b*M+i]
    for (int idx = tid; idx < N1 * M1; idx += blockDim.x) {
        int j = idx / N1, i = idx - j * N1;
        cost[i * M1 + j] = Cg[(size_t)(b * QQ + j) * NT + b * MM + i];
    }
    if (tid < N1 + 1) u[tid] = 0.f;
    if (tid <= M1) { v[tid] = 0.f; p[tid] = -1; }
    __syncthreads();

    for (int i = 0; i < N1; ++i) {
        if (tid <= M1) { minv[tid] = FLT_MAX; used[tid] = 0; }
        if (tid == 0) { p[M1] = i; s_j0 = M1; }
        __syncthreads();

        while (true) {
            int j0 = s_j0;
            if (p[j0] == -1) break;
            int i0 = p[j0];
            float ui0 = u[i0];
            if (tid == j0) used[tid] = 1;

            unsigned long long local = 0xFFFFFFFFFFFFFFFFULL;
            if (tid < M1 && !used[tid]) {
                float cur = cost[i0 * M1 + tid] - ui0 - v[tid];
                if (cur < minv[tid]) { minv[tid] = cur; way[tid] = j0; }
                float mv = minv[tid];
                unsigned int bits = __float_as_uint(mv);
                unsigned int key = (bits & 0x80000000u) ? ~bits : (bits | 0x80000000u);
                local = ((unsigned long long)key << 32) | (unsigned int)tid;
            }
            // warp reduce min (value, index packed; low bits = index -> first-min tiebreak)
            unsigned long long bst = local;
            #pragma unroll
            for (int o = 16; o; o >>= 1) {
                unsigned long long other = __shfl_down_sync(0xffffffffu, bst, o);
                if (other < bst) bst = other;
            }
            if ((tid & 31) == 0) s_red[tid >> 5] = bst;
            __syncthreads();
            if (tid == 0) {
                unsigned long long bb = s_red[0];
                #pragma unroll
                for (int w = 1; w < 10; ++w) if (s_red[w] < bb) bb = s_red[w];
                s_j1 = (int)(bb & 0xffffffffu);
                unsigned int key = (unsigned int)(bb >> 32);
                unsigned int bits = (key & 0x80000000u) ? (key ^ 0x80000000u) : ~key;
                s_delta = __uint_as_float(bits);
            }
            __syncthreads();
            int j1 = s_j1;
            float delta = s_delta;
            if (tid <= M1) {
                if (used[tid]) { v[tid] -= delta; u[p[tid]] += delta; }
                else if (tid < M1) minv[tid] -= delta;
            }
            if (tid == 0) s_j0 = j1;
            __syncthreads();
        }

        // augment (serial, short path)
        if (tid == 0) {
            int j0 = s_j0;
            while (j0 != M1) { int j1 = way[j0]; p[j0] = p[j1]; j0 = j1; }
        }
        __syncthreads();
    }

    // q[i] = column assigned to row i
    if (tid < M1 && p[tid] >= 0) qrow[p[tid]] = tid;
    __syncthreads();
    // rank-sort (distinct values) -> pred_idx sorted ascending, gt_idx = order
    if (tid < N1) {
        int qi = qrow[tid];
        int rank = 0;
        #pragma unroll 10
        for (int k = 0; k < N1; k++) rank += (qrow[k] < qi);
        out[b * MM + rank] = (float)qi;                 // pred_idx
        out[NT + b * MM + rank] = (float)tid;           // gt_idx
    }
}

// ---------------------------------------------------------------------------
extern "C" void kernel_launch(void* const* d_in, const int* in_sizes, int n_in,
                              void* d_out, int out_size) {
    const float* pred_logits = (const float*)d_in[0];
    const float* pred_boxes  = (const float*)d_in[1];
    const int*   tgt_labels  = (const int*)d_in[2];
    const float* tgt_boxes   = (const float*)d_in[3];
    float* out = (float*)d_out;
    float* Cout = out + 2 * NT;   // C starts after pred_idx (1600) + gt_idx (1600)

    // A: softmax
    {
        int threads = 256;
        int blocks = (NP * 32 + threads - 1) / threads;
        softmax_kernel<<<blocks, threads>>>(pred_logits);
    }
    // B: cost matrix
    {
        dim3 block(64, 4);
        dim3 grid(NP / 16, NT / 64);
        cost_kernel<<<grid, block>>>(pred_boxes, tgt_labels, tgt_boxes, Cout);
    }
    // C: hungarian
    {
        size_t smem = (size_t)(N1 * M1 + (N1 + 1) + 2 * (M1 + 1)) * sizeof(float)
                    + (size_t)(3 * (M1 + 1) + N1) * sizeof(int);
        cudaFuncSetAttribute(hungarian_kernel,
                             cudaFuncAttributeMaxDynamicSharedMemorySize, (int)smem);
        hungarian_kernel<<<BB, 320, smem>>>(Cout, out);
    }
}

// round 6
// speedup vs baseline: 1.0423x; 1.0423x over previous
#include <cuda_runtime.h>
#include <float.h>

#define BB 32
#define QQ 300
#define NCLS 92
#define MM 50
#define NP (BB*QQ)      // 9600 pred rows
#define NT (BB*MM)      // 1600 target cols
#define M1 300          // m (columns in hungarian)
#define N1 50           // n (rows in hungarian)

// Normalized softmax probabilities, 9600 x 92 (3.53 MB scratch)
__device__ float g_probs[NP * NCLS];

// ---------------------------------------------------------------------------
// Kernel A: row softmax of logits. One warp per row.
// ---------------------------------------------------------------------------
__global__ void softmax_kernel(const float* __restrict__ logits) {
    int warp = (blockIdx.x * blockDim.x + threadIdx.x) >> 5;
    int lane = threadIdx.x & 31;
    if (warp >= NP) return;
    const float* row = logits + (size_t)warp * NCLS;
    float x0 = row[lane];
    float x1 = row[lane + 32];
    float x2 = (lane < NCLS - 64) ? row[lane + 64] : -FLT_MAX;
    float mx = fmaxf(fmaxf(x0, x1), x2);
    #pragma unroll
    for (int o = 16; o; o >>= 1) mx = fmaxf(mx, __shfl_xor_sync(0xffffffffu, mx, o));
    float e0 = expf(x0 - mx), e1 = expf(x1 - mx);
    float e2 = (lane < NCLS - 64) ? expf(x2 - mx) : 0.f;
    float s = e0 + e1 + e2;
    #pragma unroll
    for (int o = 16; o; o >>= 1) s += __shfl_xor_sync(0xffffffffu, s, o);
    float inv = 1.f / s;
    float* prow = g_probs + (size_t)warp * NCLS;
    prow[lane] = e0 * inv;
    prow[lane + 32] = e1 * inv;
    if (lane < NCLS - 64) prow[lane + 64] = e2 * inv;
}

// ---------------------------------------------------------------------------
// Kernel B: full cross cost matrix C[9600][1600].
// Tile: 16 preds x 64 targets per block; block (64,4), each thread 4 preds.
// ---------------------------------------------------------------------------
__global__ void cost_kernel(const float* __restrict__ pred_boxes,
                            const int*   __restrict__ tgt_labels,
                            const float* __restrict__ tgt_boxes,
                            float* __restrict__ Cout) {
    __shared__ float s_probs[16 * NCLS];
    __shared__ float s_pcx[16][4];   // pred cxcywh
    __shared__ float s_pxy[16][4];   // pred xyxy
    __shared__ float s_parea[16];
    __shared__ float s_tcx[64][4];
    __shared__ float s_txy[64][4];
    __shared__ float s_tarea[64];
    __shared__ int   s_tl[64];

    int tid = threadIdx.y * 64 + threadIdx.x;
    int p0 = blockIdx.x * 16;
    int t0 = blockIdx.y * 64;

    for (int i = tid; i < 16 * NCLS; i += 256) {
        int pp = i / NCLS, c = i - pp * NCLS;
        s_probs[pp * NCLS + c] = g_probs[(size_t)(p0 + pp) * NCLS + c];
    }
    if (tid < 16) {
        const float* b = pred_boxes + (size_t)(p0 + tid) * 4;
        float cx = b[0], cy = b[1], w = b[2], h = b[3];
        s_pcx[tid][0] = cx; s_pcx[tid][1] = cy; s_pcx[tid][2] = w; s_pcx[tid][3] = h;
        float x0 = cx - 0.5f * w, y0 = cy - 0.5f * h;
        float x1 = cx + 0.5f * w, y1 = cy + 0.5f * h;
        s_pxy[tid][0] = x0; s_pxy[tid][1] = y0; s_pxy[tid][2] = x1; s_pxy[tid][3] = y1;
        s_parea[tid] = (x1 - x0) * (y1 - y0);
    }
    if (tid < 64) {
        const float* b = tgt_boxes + (size_t)(t0 + tid) * 4;
        float cx = b[0], cy = b[1], w = b[2], h = b[3];
        s_tcx[tid][0] = cx; s_tcx[tid][1] = cy; s_tcx[tid][2] = w; s_tcx[tid][3] = h;
        float x0 = cx - 0.5f * w, y0 = cy - 0.5f * h;
        float x1 = cx + 0.5f * w, y1 = cy + 0.5f * h;
        s_txy[tid][0] = x0; s_txy[tid][1] = y0; s_txy[tid][2] = x1; s_txy[tid][3] = y1;
        s_tarea[tid] = (x1 - x0) * (y1 - y0);
        s_tl[tid] = tgt_labels[t0 + tid];
    }
    __syncthreads();

    int tx = threadIdx.x;
    int lab = s_tl[tx];
    float tcx = s_tcx[tx][0], tcy = s_tcx[tx][1], tw = s_tcx[tx][2], th = s_tcx[tx][3];
    float bx0 = s_txy[tx][0], by0 = s_txy[tx][1], bx1 = s_txy[tx][2], by1 = s_txy[tx][3];
    float areaB = s_tarea[tx];
    int col = t0 + tx;

    #pragma unroll
    for (int k = 0; k < 4; k++) {
        int pp = threadIdx.y + k * 4;
        float cc = -s_probs[pp * NCLS + lab];
        float cb = fabsf(s_pcx[pp][0] - tcx) + fabsf(s_pcx[pp][1] - tcy)
                 + fabsf(s_pcx[pp][2] - tw)  + fabsf(s_pcx[pp][3] - th);
        float ax0 = s_pxy[pp][0], ay0 = s_pxy[pp][1], ax1 = s_pxy[pp][2], ay1 = s_pxy[pp][3];
        float areaA = s_parea[pp];
        float ix0 = fmaxf(ax0, bx0), iy0 = fmaxf(ay0, by0);
        float ix1 = fminf(ax1, bx1), iy1 = fminf(ay1, by1);
        float iw = fmaxf(ix1 - ix0, 0.f), ih = fmaxf(iy1 - iy0, 0.f);
        float inter = iw * ih;
        float uni = areaA + areaB - inter;
        float iou = inter / uni;
        float ex0 = fminf(ax0, bx0), ey0 = fminf(ay0, by0);
        float ex1 = fmaxf(ax1, bx1), ey1 = fmaxf(ey1 > ey0 ? ay1 : ay1, by1);
        // (no-op ternary removed below — keep exact formula)
        ex1 = fmaxf(ax1, bx1); ey1 = fmaxf(ay1, by1);
        float ew = fmaxf(ex1 - ex0, 0.f), eh = fmaxf(ey1 - ey0, 0.f);
        float areaE = ew * eh;
        float giou = iou - (areaE - uni) / areaE;
        float c = 1.0f * cc + 5.0f * cb + 2.0f * (-giou);
        Cout[(size_t)(p0 + pp) * NT + col] = c;
    }
}

// ---------------------------------------------------------------------------
// Kernel C: warp-level Jonker-Volgenant with greedy dual initialization.
// One block (256 thr) per batch; load phase uses all threads, solve uses
// warp 0 only. Lane t owns columns j = t, t+32, ..., t+288 (<=10 cols).
// minv/v/used live in registers; argmin is a packed shfl_xor reduction.
// ---------------------------------------------------------------------------
__global__ void hungarian_kernel(const float* __restrict__ Cg, float* __restrict__ out) {
    extern __shared__ float smem[];
    float* cost = smem;                 // 50*300
    float* u    = cost + N1 * M1;       // 51
    int*   p    = (int*)(u + (N1 + 1)); // 301
    int*   way  = p + (M1 + 1);         // 300
    int*   pend = way + M1;             // 50
    int*   qrow = pend + N1;            // 50
    __shared__ int s_npend;

    int b = blockIdx.x;
    int tid = threadIdx.x;

    // load per-batch cost slice: cost[i][j] = C[b*Q+j][b*M+i]
    for (int idx = tid; idx < N1 * M1; idx += 256) {
        int j = idx / N1, i = idx - j * N1;
        cost[i * M1 + j] = Cg[(size_t)(b * QQ + j) * NT + b * MM + i];
    }
    for (int idx = tid; idx < N1 + 1; idx += 256) u[idx] = 0.f;
    for (int idx = tid; idx <= M1; idx += 256) p[idx] = -1;   // FIX: cover all 301
    if (tid == 0) s_npend = 0;
    __syncthreads();
    if (tid >= 32) return;   // warp 0 solves alone

    int lane = tid;
    float v_r[10], minv_r[10];
    #pragma unroll
    for (int k = 0; k < 10; k++) v_r[k] = 0.f;

    // ---- greedy init: u[i] = row min; assign row to argmin col if free ----
    for (int i = 0; i < N1; ++i) {
        unsigned long long local = ~0ull;
        #pragma unroll
        for (int k = 0; k < 10; k++) {
            int j = lane + 32 * k;
            if (j < M1) {
                unsigned bits = __float_as_uint(cost[i * M1 + j]);
                unsigned key = (bits & 0x80000000u) ? ~bits : (bits | 0x80000000u);
                unsigned long long cand = ((unsigned long long)key << 32) | (unsigned)j;
                if (cand < local) local = cand;
            }
        }
        #pragma unroll
        for (int o = 16; o; o >>= 1) {
            unsigned long long oth = __shfl_xor_sync(0xffffffffu, local, o);
            if (oth < local) local = oth;
        }
        if (lane == 0) {
            int jstar = (int)(local & 0xffffffffu);
            unsigned key = (unsigned)(local >> 32);
            unsigned bits = (key & 0x80000000u) ? (key ^ 0x80000000u) : ~key;
            u[i] = __uint_as_float(bits);
            if (p[jstar] == -1) p[jstar] = i;
            else { pend[s_npend] = i; s_npend = s_npend + 1; }
        }
        __syncwarp();
    }
    int npend = s_npend;

    // ---- Dijkstra augmenting paths for the few unassigned rows ----
    for (int t = 0; t < npend; ++t) {
        int irow = pend[t];
        if (lane == 0) p[M1] = irow;
        #pragma unroll
        for (int k = 0; k < 10; k++) minv_r[k] = FLT_MAX;
        unsigned used_mask = 0;
        int j0 = M1;
        __syncwarp();

        while (true) {
            int i0 = p[j0];
            if (i0 == -1) break;
            if (j0 < M1 && (j0 & 31) == lane) used_mask |= 1u << (j0 >> 5);
            float ui0 = u[i0];
            unsigned long long local = ~0ull;
            #pragma unroll
            for (int k = 0; k < 10; k++) {
                int j = lane + 32 * k;
                if (j < M1 && !((used_mask >> k) & 1u)) {
                    float cur = cost[i0 * M1 + j] - ui0 - v_r[k];
                    if (cur < minv_r[k]) { minv_r[k] = cur; way[j] = j0; }
                    unsigned bits = __float_as_uint(minv_r[k]);
                    unsigned key = (bits & 0x80000000u) ? ~bits : (bits | 0x80000000u);
                    unsigned long long cand = ((unsigned long long)key << 32) | (unsigned)j;
                    if (cand < local) local = cand;
                }
            }
            #pragma unroll
            for (int o = 16; o; o >>= 1) {
                unsigned long long oth = __shfl_xor_sync(0xffffffffu, local, o);
                if (oth < local) local = oth;
            }
            int j1 = (int)(local & 0xffffffffu);
            unsigned key = (unsigned)(local >> 32);
            unsigned bits2 = (key & 0x80000000u) ? (key ^ 0x80000000u) : ~key;
            float delta = __uint_as_float(bits2);

            // dual update: used cols -> v -= delta, u[p[j]] += delta;
            // unused cols -> minv -= delta; virtual col m -> u[irow] += delta.
            #pragma unroll
            for (int k = 0; k < 10; k++) {
                int j = lane + 32 * k;
                if (j < M1) {
                    if ((used_mask >> k) & 1u) { v_r[k] -= delta; u[p[j]] += delta; }
                    else minv_r[k] -= delta;
                }
            }
            if (lane == 0) u[irow] += delta;
            j0 = j1;
            __syncwarp();
        }

        // augment (short chain, serial)
        if (lane == 0) {
            int jj = j0;
            while (jj != M1) { int jn = way[jj]; p[jj] = p[jn]; jj = jn; }
        }
        __syncwarp();
    }

    // ---- emit pred_idx / gt_idx (sorted by assigned column) ----
    #pragma unroll
    for (int k = 0; k < 10; k++) {
        int j = lane + 32 * k;
        if (j < M1) { int r = p[j]; if (r >= 0) qrow[r] = j; }
    }
    __syncwarp();
    for (int r = lane; r < N1; r += 32) {
        int qi = qrow[r];
        int rank = 0;
        #pragma unroll 10
        for (int k2 = 0; k2 < N1; k2++) rank += (qrow[k2] < qi);
        out[b * MM + rank] = (float)qi;            // pred_idx
        out[NT + b * MM + rank] = (float)r;        // gt_idx
    }
}

// ---------------------------------------------------------------------------
extern "C" void kernel_launch(void* const* d_in, const int* in_sizes, int n_in,
                              void* d_out, int out_size) {
    const float* pred_logits = (const float*)d_in[0];
    const float* pred_boxes  = (const float*)d_in[1];
    const int*   tgt_labels  = (const int*)d_in[2];
    const float* tgt_boxes   = (const float*)d_in[3];
    float* out = (float*)d_out;
    float* Cout = out + 2 * NT;   // C starts after pred_idx (1600) + gt_idx (1600)

    // A: softmax
    {
        int threads = 256;
        int blocks = (NP * 32 + threads - 1) / threads;
        softmax_kernel<<<blocks, threads>>>(pred_logits);
    }
    // B: cost matrix
    {
        dim3 block(64, 4);
        dim3 grid(NP / 16, NT / 64);
        cost_kernel<<<grid, block>>>(pred_boxes, tgt_labels, tgt_boxes, Cout);
    }
    // C: hungarian (warp JV + greedy init)
    {
        size_t smem = (size_t)(N1 * M1 + (N1 + 1)) * sizeof(float)
                    + (size_t)((M1 + 1) + M1 + N1 + N1) * sizeof(int);
        cudaFuncSetAttribute(hungarian_kernel,
                             cudaFuncAttributeMaxDynamicSharedMemorySize, (int)smem);
        hungarian_kernel<<<BB, 256, smem>>>(Cout, out);
    }
}

// round 7
// speedup vs baseline: 1.2726x; 1.2210x over previous
#include <cuda_runtime.h>
#include <float.h>

#define BB 32
#define QQ 300
#define NCLS 92
#define MM 50
#define NP (BB*QQ)      // 9600 pred rows
#define NT (BB*MM)      // 1600 target cols
#define M1 300          // m (columns in hungarian)
#define N1 50           // n (rows in hungarian)

// Normalized softmax probabilities, 9600 x 92 (3.53 MB scratch)
__device__ float g_probs[NP * NCLS];

// ---------------------------------------------------------------------------
// Kernel A: row softmax of logits. One warp per row.
// ---------------------------------------------------------------------------
__global__ void softmax_kernel(const float* __restrict__ logits) {
    int warp = (blockIdx.x * blockDim.x + threadIdx.x) >> 5;
    int lane = threadIdx.x & 31;
    if (warp >= NP) return;
    const float* row = logits + (size_t)warp * NCLS;
    float x0 = row[lane];
    float x1 = row[lane + 32];
    float x2 = (lane < NCLS - 64) ? row[lane + 64] : -FLT_MAX;
    float mx = fmaxf(fmaxf(x0, x1), x2);
    #pragma unroll
    for (int o = 16; o; o >>= 1) mx = fmaxf(mx, __shfl_xor_sync(0xffffffffu, mx, o));
    float e0 = __expf(x0 - mx), e1 = __expf(x1 - mx);
    float e2 = (lane < NCLS - 64) ? __expf(x2 - mx) : 0.f;
    float s = e0 + e1 + e2;
    #pragma unroll
    for (int o = 16; o; o >>= 1) s += __shfl_xor_sync(0xffffffffu, s, o);
    float inv = __fdividef(1.f, s);
    float* prow = g_probs + (size_t)warp * NCLS;
    prow[lane] = e0 * inv;
    prow[lane + 32] = e1 * inv;
    if (lane < NCLS - 64) prow[lane + 64] = e2 * inv;
}

// ---------------------------------------------------------------------------
// Kernel B: full cross cost matrix C[9600][1600].
// Tile: 16 preds x 64 targets per block; block (64,4), each thread 4 preds.
// Fast divisions (MUFU.RCP based) — rel err ~2^-22, way under tolerance.
// ---------------------------------------------------------------------------
__global__ void cost_kernel(const float* __restrict__ pred_boxes,
                            const int*   __restrict__ tgt_labels,
                            const float* __restrict__ tgt_boxes,
                            float* __restrict__ Cout) {
    __shared__ float s_probs[16 * NCLS];
    __shared__ float s_pcx[16][4];   // pred cxcywh
    __shared__ float s_pxy[16][4];   // pred xyxy
    __shared__ float s_parea[16];
    __shared__ float s_tcx[64][4];
    __shared__ float s_txy[64][4];
    __shared__ float s_tarea[64];
    __shared__ int   s_tl[64];

    int tid = threadIdx.y * 64 + threadIdx.x;
    int p0 = blockIdx.x * 16;
    int t0 = blockIdx.y * 64;

    for (int i = tid; i < 16 * NCLS; i += 256) {
        int pp = i / NCLS, c = i - pp * NCLS;
        s_probs[pp * NCLS + c] = g_probs[(size_t)(p0 + pp) * NCLS + c];
    }
    if (tid < 16) {
        const float* b = pred_boxes + (size_t)(p0 + tid) * 4;
        float cx = b[0], cy = b[1], w = b[2], h = b[3];
        s_pcx[tid][0] = cx; s_pcx[tid][1] = cy; s_pcx[tid][2] = w; s_pcx[tid][3] = h;
        float x0 = cx - 0.5f * w, y0 = cy - 0.5f * h;
        float x1 = cx + 0.5f * w, y1 = cy + 0.5f * h;
        s_pxy[tid][0] = x0; s_pxy[tid][1] = y0; s_pxy[tid][2] = x1; s_pxy[tid][3] = y1;
        s_parea[tid] = (x1 - x0) * (y1 - y0);
    }
    if (tid < 64) {
        const float* b = tgt_boxes + (size_t)(t0 + tid) * 4;
        float cx = b[0], cy = b[1], w = b[2], h = b[3];
        s_tcx[tid][0] = cx; s_tcx[tid][1] = cy; s_tcx[tid][2] = w; s_tcx[tid][3] = h;
        float x0 = cx - 0.5f * w, y0 = cy - 0.5f * h;
        float x1 = cx + 0.5f * w, y1 = cy + 0.5f * h;
        s_txy[tid][0] = x0; s_txy[tid][1] = y0; s_txy[tid][2] = x1; s_txy[tid][3] = y1;
        s_tarea[tid] = (x1 - x0) * (y1 - y0);
        s_tl[tid] = tgt_labels[t0 + tid];
    }
    __syncthreads();

    int tx = threadIdx.x;
    int lab = s_tl[tx];
    float tcx = s_tcx[tx][0], tcy = s_tcx[tx][1], tw = s_tcx[tx][2], th = s_tcx[tx][3];
    float bx0 = s_txy[tx][0], by0 = s_txy[tx][1], bx1 = s_txy[tx][2], by1 = s_txy[tx][3];
    float areaB = s_tarea[tx];
    int col = t0 + tx;

    #pragma unroll
    for (int k = 0; k < 4; k++) {
        int pp = threadIdx.y + k * 4;
        float cc = -s_probs[pp * NCLS + lab];
        float cb = fabsf(s_pcx[pp][0] - tcx) + fabsf(s_pcx[pp][1] - tcy)
                 + fabsf(s_pcx[pp][2] - tw)  + fabsf(s_pcx[pp][3] - th);
        float ax0 = s_pxy[pp][0], ay0 = s_pxy[pp][1], ax1 = s_pxy[pp][2], ay1 = s_pxy[pp][3];
        float areaA = s_parea[pp];
        float ix0 = fmaxf(ax0, bx0), iy0 = fmaxf(ay0, by0);
        float ix1 = fminf(ax1, bx1), iy1 = fminf(ay1, by1);
        float iw = fmaxf(ix1 - ix0, 0.f), ih = fmaxf(iy1 - iy0, 0.f);
        float inter = iw * ih;
        float uni = areaA + areaB - inter;
        float iou = __fdividef(inter, uni);
        float ex0 = fminf(ax0, bx0), ey0 = fminf(ay0, by0);
        float ex1 = fmaxf(ax1, bx1), ey1 = fmaxf(ay1, by1);
        float ew = fmaxf(ex1 - ex0, 0.f), eh = fmaxf(ey1 - ey0, 0.f);
        float areaE = ew * eh;
        float giou = iou - __fdividef(areaE - uni, areaE);
        float c = 1.0f * cc + 5.0f * cb + 2.0f * (-giou);
        Cout[(size_t)(p0 + pp) * NT + col] = c;
    }
}

// ---------------------------------------------------------------------------
// Kernel C: warp-level Jonker-Volgenant with greedy dual initialization.
// One block (256 thr) per batch; load phase uses all threads, solve uses
// warp 0 only. Lane t owns columns j = t, t+32, ..., t+288 (<=10 cols).
// minv/v/used live in registers; argmin is a packed shfl_xor reduction.
// ---------------------------------------------------------------------------
__global__ void hungarian_kernel(const float* __restrict__ Cg, float* __restrict__ out) {
    extern __shared__ float smem[];
    float* cost = smem;                 // 50*300
    float* u    = cost + N1 * M1;       // 51
    int*   p    = (int*)(u + (N1 + 1)); // 301
    int*   way  = p + (M1 + 1);         // 300
    int*   pend = way + M1;             // 50
    int*   qrow = pend + N1;            // 50
    __shared__ int s_npend;

    int b = blockIdx.x;
    int tid = threadIdx.x;

    // load per-batch cost slice: cost[i][j] = C[b*Q+j][b*M+i]
    for (int idx = tid; idx < N1 * M1; idx += 256) {
        int j = idx / N1, i = idx - j * N1;
        cost[i * M1 + j] = Cg[(size_t)(b * QQ + j) * NT + b * MM + i];
    }
    for (int idx = tid; idx < N1 + 1; idx += 256) u[idx] = 0.f;
    for (int idx = tid; idx <= M1; idx += 256) p[idx] = -1;
    if (tid == 0) s_npend = 0;
    __syncthreads();
    if (tid >= 32) return;   // warp 0 solves alone

    int lane = tid;
    float v_r[10], minv_r[10];
    #pragma unroll
    for (int k = 0; k < 10; k++) v_r[k] = 0.f;

    // ---- greedy init: u[i] = row min; assign row to argmin col if free ----
    for (int i = 0; i < N1; ++i) {
        unsigned long long local = ~0ull;
        #pragma unroll
        for (int k = 0; k < 10; k++) {
            int j = lane + 32 * k;
            if (j < M1) {
                unsigned bits = __float_as_uint(cost[i * M1 + j]);
                unsigned key = (bits & 0x80000000u) ? ~bits : (bits | 0x80000000u);
                unsigned long long cand = ((unsigned long long)key << 32) | (unsigned)j;
                if (cand < local) local = cand;
            }
        }
        #pragma unroll
        for (int o = 16; o; o >>= 1) {
            unsigned long long oth = __shfl_xor_sync(0xffffffffu, local, o);
            if (oth < local) local = oth;
        }
        if (lane == 0) {
            int jstar = (int)(local & 0xffffffffu);
            unsigned key = (unsigned)(local >> 32);
            unsigned bits = (key & 0x80000000u) ? (key ^ 0x80000000u) : ~key;
            u[i] = __uint_as_float(bits);
            if (p[jstar] == -1) p[jstar] = i;
            else { pend[s_npend] = i; s_npend = s_npend + 1; }
        }
        __syncwarp();
    }
    int npend = s_npend;

    // ---- Dijkstra augmenting paths for the few unassigned rows ----
    for (int t = 0; t < npend; ++t) {
        int irow = pend[t];
        if (lane == 0) p[M1] = irow;
        #pragma unroll
        for (int k = 0; k < 10; k++) minv_r[k] = FLT_MAX;
        unsigned used_mask = 0;
        int j0 = M1;
        __syncwarp();

        while (true) {
            int i0 = p[j0];
            if (i0 == -1) break;
            if (j0 < M1 && (j0 & 31) == lane) used_mask |= 1u << (j0 >> 5);
            float ui0 = u[i0];
            unsigned long long local = ~0ull;
            #pragma unroll
            for (int k = 0; k < 10; k++) {
                int j = lane + 32 * k;
                if (j < M1 && !((used_mask >> k) & 1u)) {
                    float cur = cost[i0 * M1 + j] - ui0 - v_r[k];
                    if (cur < minv_r[k]) { minv_r[k] = cur; way[j] = j0; }
                    unsigned bits = __float_as_uint(minv_r[k]);
                    unsigned key = (bits & 0x80000000u) ? ~bits : (bits | 0x80000000u);
                    unsigned long long cand = ((unsigned long long)key << 32) | (unsigned)j;
                    if (cand < local) local = cand;
                }
            }
            #pragma unroll
            for (int o = 16; o; o >>= 1) {
                unsigned long long oth = __shfl_xor_sync(0xffffffffu, local, o);
                if (oth < local) local = oth;
            }
            int j1 = (int)(local & 0xffffffffu);
            unsigned key = (unsigned)(local >> 32);
            unsigned bits2 = (key & 0x80000000u) ? (key ^ 0x80000000u) : ~key;
            float delta = __uint_as_float(bits2);

            // dual update: used cols -> v -= delta, u[p[j]] += delta;
            // unused cols -> minv -= delta; virtual col m -> u[irow] += delta.
            #pragma unroll
            for (int k = 0; k < 10; k++) {
                int j = lane + 32 * k;
                if (j < M1) {
                    if ((used_mask >> k) & 1u) { v_r[k] -= delta; u[p[j]] += delta; }
                    else minv_r[k] -= delta;
                }
            }
            if (lane == 0) u[irow] += delta;
            j0 = j1;
            __syncwarp();
        }

        // augment (short chain, serial)
        if (lane == 0) {
            int jj = j0;
            while (jj != M1) { int jn = way[jj]; p[jj] = p[jn]; jj = jn; }
        }
        __syncwarp();
    }

    // ---- emit pred_idx / gt_idx (sorted by assigned column) ----
    #pragma unroll
    for (int k = 0; k < 10; k++) {
        int j = lane + 32 * k;
        if (j < M1) { int r = p[j]; if (r >= 0) qrow[r] = j; }
    }
    __syncwarp();
    for (int r = lane; r < N1; r += 32) {
        int qi = qrow[r];
        int rank = 0;
        #pragma unroll 10
        for (int k2 = 0; k2 < N1; k2++) rank += (qrow[k2] < qi);
        out[b * MM + rank] = (float)qi;            // pred_idx
        out[NT + b * MM + rank] = (float)r;        // gt_idx
    }
}

// ---------------------------------------------------------------------------
extern "C" void kernel_launch(void* const* d_in, const int* in_sizes, int n_in,
                              void* d_out, int out_size) {
    const float* pred_logits = (const float*)d_in[0];
    const float* pred_boxes  = (const float*)d_in[1];
    const int*   tgt_labels  = (const int*)d_in[2];
    const float* tgt_boxes   = (const float*)d_in[3];
    float* out = (float*)d_out;
    float* Cout = out + 2 * NT;   // C starts after pred_idx (1600) + gt_idx (1600)

    // A: softmax
    {
        int threads = 256;
        int blocks = (NP * 32 + threads - 1) / threads;
        softmax_kernel<<<blocks, threads>>>(pred_logits);
    }
    // B: cost matrix
    {
        dim3 block(64, 4);
        dim3 grid(NP / 16, NT / 64);
        cost_kernel<<<grid, block>>>(pred_boxes, tgt_labels, tgt_boxes, Cout);
    }
    // C: hungarian (warp JV + greedy init)
    {
        size_t smem = (size_t)(N1 * M1 + (N1 + 1)) * sizeof(float)
                    + (size_t)((M1 + 1) + M1 + N1 + N1) * sizeof(int);
        cudaFuncSetAttribute(hungarian_kernel,
                             cudaFuncAttributeMaxDynamicSharedMemorySize, (int)smem);
        hungarian_kernel<<<BB, 256, smem>>>(Cout, out);
    }
}